// round 1
// baseline (speedup 1.0000x reference)
#include <cuda_runtime.h>

#define BATCH 8
#define NROWS 10000
#define CDIM 256
#define CHUNKS 40
#define ROWS_PER_CHUNK 250   // 10000 / 40
#define LN_EPS 1e-5f

// Scratch (allocation-free rule: __device__ globals)
__device__ float g_partial[BATCH][CHUNKS][CDIM];
__device__ float g_agg[BATCH][CDIM];

// ---------------------------------------------------------------------------
// Kernel 1: partial column sums. grid (BATCH, CHUNKS), 256 threads.
// Thread t owns column t; reads are fully coalesced (warp covers 128B/row).
// ---------------------------------------------------------------------------
__global__ void col_sum_kernel(const float* __restrict__ x) {
    const int b = blockIdx.x;
    const int ch = blockIdx.y;
    const int t = threadIdx.x;
    const float* base = x + ((size_t)b * NROWS + (size_t)ch * ROWS_PER_CHUNK) * CDIM + t;
    float s = 0.0f;
#pragma unroll 5
    for (int r = 0; r < ROWS_PER_CHUNK; ++r) {
        s += base[(size_t)r * CDIM];
    }
    g_partial[b][ch][t] = s;
}

// ---------------------------------------------------------------------------
// Kernel 2: finish mean + tiny GEMM  agg[b][c] = dot(mean[b,:], W[c,:]) + bias
// grid (BATCH), 256 threads (8 warps). Warp w computes outputs c = w, w+8,...
// Lane-strided k -> coalesced W reads.
// ---------------------------------------------------------------------------
__global__ void mean_gemm_kernel(const float* __restrict__ W,
                                 const float* __restrict__ bias) {
    const int b = blockIdx.x;
    const int t = threadIdx.x;
    __shared__ float smean[CDIM];

    float s = 0.0f;
#pragma unroll
    for (int j = 0; j < CHUNKS; ++j) s += g_partial[b][j][t];
    smean[t] = s * (1.0f / (float)NROWS);
    __syncthreads();

    const int warp = t >> 5;
    const int lane = t & 31;
    for (int c = warp; c < CDIM; c += 8) {
        const float* wr = W + (size_t)c * CDIM;
        float d = 0.0f;
#pragma unroll
        for (int k = lane; k < CDIM; k += 32) {
            d += wr[k] * smean[k];
        }
#pragma unroll
        for (int off = 16; off > 0; off >>= 1)
            d += __shfl_down_sync(0xffffffffu, d, off);
        if (lane == 0) g_agg[b][c] = d + bias[c];
    }
}

// ---------------------------------------------------------------------------
// Kernel 3: fused residual + LayerNorm. One warp per row; lane owns 8
// contiguous floats (2x float4) -> fully coalesced 1KB row transactions.
// grid = (BATCH*NROWS)/8 blocks of 256 threads (8 warps).
// ---------------------------------------------------------------------------
__global__ void resid_ln_kernel(const float* __restrict__ x,
                                const float* __restrict__ gamma,
                                const float* __restrict__ beta,
                                float* __restrict__ out) {
    const int warp = threadIdx.x >> 5;
    const int lane = threadIdx.x & 31;
    const long row = (long)blockIdx.x * 8 + warp;
    if (row >= (long)BATCH * NROWS) return;
    const int b = (int)(row / NROWS);

    const float4* xr = (const float4*)(x + row * (long)CDIM);
    const float4* ar = (const float4*)(&g_agg[b][0]);

    float4 x0 = xr[lane * 2 + 0];
    float4 x1 = xr[lane * 2 + 1];
    float4 a0 = ar[lane * 2 + 0];
    float4 a1 = ar[lane * 2 + 1];

    float y[8];
    y[0] = x0.x + a0.x; y[1] = x0.y + a0.y; y[2] = x0.z + a0.z; y[3] = x0.w + a0.w;
    y[4] = x1.x + a1.x; y[5] = x1.y + a1.y; y[6] = x1.z + a1.z; y[7] = x1.w + a1.w;

    float sum = 0.0f, sumsq = 0.0f;
#pragma unroll
    for (int i = 0; i < 8; ++i) { sum += y[i]; sumsq += y[i] * y[i]; }
#pragma unroll
    for (int off = 16; off > 0; off >>= 1) {
        sum   += __shfl_xor_sync(0xffffffffu, sum, off);
        sumsq += __shfl_xor_sync(0xffffffffu, sumsq, off);
    }

    const float mu = sum * (1.0f / (float)CDIM);
    const float var = sumsq * (1.0f / (float)CDIM) - mu * mu;
    const float rstd = rsqrtf(var + LN_EPS);

    const float4* gr = (const float4*)gamma;
    const float4* br = (const float4*)beta;
    float4 g0 = gr[lane * 2 + 0];
    float4 g1 = gr[lane * 2 + 1];
    float4 b0 = br[lane * 2 + 0];
    float4 b1 = br[lane * 2 + 1];

    float4 o0, o1;
    o0.x = (y[0] - mu) * rstd * g0.x + b0.x;
    o0.y = (y[1] - mu) * rstd * g0.y + b0.y;
    o0.z = (y[2] - mu) * rstd * g0.z + b0.z;
    o0.w = (y[3] - mu) * rstd * g0.w + b0.w;
    o1.x = (y[4] - mu) * rstd * g1.x + b1.x;
    o1.y = (y[5] - mu) * rstd * g1.y + b1.y;
    o1.z = (y[6] - mu) * rstd * g1.z + b1.z;
    o1.w = (y[7] - mu) * rstd * g1.w + b1.w;

    float4* orow = (float4*)(out + row * (long)CDIM);
    orow[lane * 2 + 0] = o0;
    orow[lane * 2 + 1] = o1;
}

extern "C" void kernel_launch(void* const* d_in, const int* in_sizes, int n_in,
                              void* d_out, int out_size) {
    const float* x     = (const float*)d_in[0];
    const float* W     = (const float*)d_in[1];
    const float* bias  = (const float*)d_in[2];
    const float* gamma = (const float*)d_in[3];
    const float* beta  = (const float*)d_in[4];
    float* out = (float*)d_out;

    dim3 g1(BATCH, CHUNKS);
    col_sum_kernel<<<g1, CDIM>>>(x);
    mean_gemm_kernel<<<BATCH, CDIM>>>(W, bias);
    const int total_rows = BATCH * NROWS;         // 80000
    resid_ln_kernel<<<total_rows / 8, 256>>>(x, gamma, beta, out);
}

// round 4
// speedup vs baseline: 1.3028x; 1.3028x over previous
#include <cuda_runtime.h>

#define BATCH 8
#define NROWS 10000
#define CDIM 256
#define CHUNKS 100
#define ROWS_PER_CHUNK 100   // 10000 / 100
#define LN_EPS 1e-5f

// Scratch (allocation-free rule: __device__ globals)
__device__ float g_partial[BATCH][CHUNKS][CDIM];
__device__ float g_agg[BATCH][CDIM];

// ---------------------------------------------------------------------------
// Kernel 1: partial column sums. grid (BATCH, CHUNKS) = 800 blocks, 256 thr.
// Thread t: float4-column (t&63), row-group (t>>6). Each thread covers rows
// congruent to rg (mod 4) within its 100-row chunk: main loop rows [0,96)
// (two independent accumulators, 12 iterations), tail row 96+rg.
// ---------------------------------------------------------------------------
__global__ void col_sum_kernel(const float* __restrict__ x) {
    const int b = blockIdx.x;
    const int ch = blockIdx.y;
    const int t = threadIdx.x;
    const int qc = t & 63;       // float4 column 0..63
    const int rg = t >> 6;       // row group 0..3

    const float4* base = (const float4*)(x
        + ((size_t)b * NROWS + (size_t)ch * ROWS_PER_CHUNK) * CDIM) + qc;

    float4 acc0 = make_float4(0.f, 0.f, 0.f, 0.f);
    float4 acc1 = make_float4(0.f, 0.f, 0.f, 0.f);
    // rows rg..92+rg step 4 (pairs): 96 = 8*12 full iterations
#pragma unroll
    for (int r = 0; r < 96; r += 8) {
        float4 v0 = base[(size_t)(r + rg) * 64];
        float4 v1 = base[(size_t)(r + rg + 4) * 64];
        acc0.x += v0.x; acc0.y += v0.y; acc0.z += v0.z; acc0.w += v0.w;
        acc1.x += v1.x; acc1.y += v1.y; acc1.z += v1.z; acc1.w += v1.w;
    }
    // tail: rows 96..99 (one per rg)
    {
        float4 v0 = base[(size_t)(96 + rg) * 64];
        acc0.x += v0.x; acc0.y += v0.y; acc0.z += v0.z; acc0.w += v0.w;
    }
    acc0.x += acc1.x; acc0.y += acc1.y; acc0.z += acc1.z; acc0.w += acc1.w;

    __shared__ float4 sh[256];
    sh[t] = acc0;
    __syncthreads();
    if (t < 64) {
        float4 a = sh[t];
        float4 c1 = sh[t + 64];
        float4 c2 = sh[t + 128];
        float4 c3 = sh[t + 192];
        a.x += c1.x + c2.x + c3.x;
        a.y += c1.y + c2.y + c3.y;
        a.z += c1.z + c2.z + c3.z;
        a.w += c1.w + c2.w + c3.w;
        ((float4*)&g_partial[b][ch][0])[t] = a;
    }
}

// ---------------------------------------------------------------------------
// Kernel 2: finish mean + tiny GEMM  agg[b][c] = dot(mean[b,:], W[c,:]) + bias
// ---------------------------------------------------------------------------
__global__ void mean_gemm_kernel(const float* __restrict__ W,
                                 const float* __restrict__ bias) {
    const int b = blockIdx.x;
    const int t = threadIdx.x;
    __shared__ float smean[CDIM];

    float s = 0.0f;
#pragma unroll 10
    for (int j = 0; j < CHUNKS; ++j) s += g_partial[b][j][t];
    smean[t] = s * (1.0f / (float)NROWS);
    __syncthreads();

    const int warp = t >> 5;
    const int lane = t & 31;
    for (int c = warp; c < CDIM; c += 8) {
        const float* wr = W + (size_t)c * CDIM;
        float d = 0.0f;
#pragma unroll
        for (int k = lane; k < CDIM; k += 32) {
            d += wr[k] * smean[k];
        }
#pragma unroll
        for (int off = 16; off > 0; off >>= 1)
            d += __shfl_down_sync(0xffffffffu, d, off);
        if (lane == 0) g_agg[b][c] = d + bias[c];
    }
}

// ---------------------------------------------------------------------------
// Kernel 3: fused residual + LayerNorm. One warp handles TWO rows (4
// independent 16B loads in flight per lane). agg/gamma/beta staged in shared.
// Block = 256 threads = 8 warps = 16 rows; 10000 = 16*625 so no block ever
// crosses a batch boundary. grid = 80000/16 = 5000 blocks.
// ---------------------------------------------------------------------------
__global__ void resid_ln_kernel(const float* __restrict__ x,
                                const float* __restrict__ gamma,
                                const float* __restrict__ beta,
                                float* __restrict__ out) {
    const int t = threadIdx.x;
    const int warp = t >> 5;
    const int lane = t & 31;
    const long row0 = (long)blockIdx.x * 16 + warp * 2;
    const int b = (int)(row0 / NROWS);   // same for all 16 rows in the block

    __shared__ float sh_agg[CDIM];
    __shared__ float sh_g[CDIM];
    __shared__ float sh_b[CDIM];
    sh_agg[t] = g_agg[b][t];
    sh_g[t] = gamma[t];
    sh_b[t] = beta[t];
    __syncthreads();

    const float4* xr0 = (const float4*)(x + row0 * (long)CDIM);
    const float4* xr1 = (const float4*)(x + (row0 + 1) * (long)CDIM);

    // 4 independent global loads issued back-to-back
    float4 p0 = xr0[lane * 2 + 0];
    float4 p1 = xr0[lane * 2 + 1];
    float4 q0 = xr1[lane * 2 + 0];
    float4 q1 = xr1[lane * 2 + 1];

    float4 a0 = ((const float4*)sh_agg)[lane * 2 + 0];
    float4 a1 = ((const float4*)sh_agg)[lane * 2 + 1];

    float ya[8], yb[8];
    ya[0] = p0.x + a0.x; ya[1] = p0.y + a0.y; ya[2] = p0.z + a0.z; ya[3] = p0.w + a0.w;
    ya[4] = p1.x + a1.x; ya[5] = p1.y + a1.y; ya[6] = p1.z + a1.z; ya[7] = p1.w + a1.w;
    yb[0] = q0.x + a0.x; yb[1] = q0.y + a0.y; yb[2] = q0.z + a0.z; yb[3] = q0.w + a0.w;
    yb[4] = q1.x + a1.x; yb[5] = q1.y + a1.y; yb[6] = q1.z + a1.z; yb[7] = q1.w + a1.w;

    float s0 = 0.f, ss0 = 0.f, s1 = 0.f, ss1 = 0.f;
#pragma unroll
    for (int i = 0; i < 8; ++i) {
        s0 += ya[i]; ss0 += ya[i] * ya[i];
        s1 += yb[i]; ss1 += yb[i] * yb[i];
    }
#pragma unroll
    for (int off = 16; off > 0; off >>= 1) {
        s0  += __shfl_xor_sync(0xffffffffu, s0, off);
        ss0 += __shfl_xor_sync(0xffffffffu, ss0, off);
        s1  += __shfl_xor_sync(0xffffffffu, s1, off);
        ss1 += __shfl_xor_sync(0xffffffffu, ss1, off);
    }

    const float inv = 1.0f / (float)CDIM;
    const float mu0 = s0 * inv;
    const float mu1 = s1 * inv;
    const float r0 = rsqrtf(ss0 * inv - mu0 * mu0 + LN_EPS);
    const float r1 = rsqrtf(ss1 * inv - mu1 * mu1 + LN_EPS);

    float4 g0 = ((const float4*)sh_g)[lane * 2 + 0];
    float4 g1 = ((const float4*)sh_g)[lane * 2 + 1];
    float4 b0 = ((const float4*)sh_b)[lane * 2 + 0];
    float4 b1 = ((const float4*)sh_b)[lane * 2 + 1];

    float4 o;
    float4* or0 = (float4*)(out + row0 * (long)CDIM);
    float4* or1 = (float4*)(out + (row0 + 1) * (long)CDIM);

    o.x = (ya[0] - mu0) * r0 * g0.x + b0.x;
    o.y = (ya[1] - mu0) * r0 * g0.y + b0.y;
    o.z = (ya[2] - mu0) * r0 * g0.z + b0.z;
    o.w = (ya[3] - mu0) * r0 * g0.w + b0.w;
    or0[lane * 2 + 0] = o;
    o.x = (ya[4] - mu0) * r0 * g1.x + b1.x;
    o.y = (ya[5] - mu0) * r0 * g1.y + b1.y;
    o.z = (ya[6] - mu0) * r0 * g1.z + b1.z;
    o.w = (ya[7] - mu0) * r0 * g1.w + b1.w;
    or0[lane * 2 + 1] = o;
    o.x = (yb[0] - mu1) * r1 * g0.x + b0.x;
    o.y = (yb[1] - mu1) * r1 * g0.y + b0.y;
    o.z = (yb[2] - mu1) * r1 * g0.z + b0.z;
    o.w = (yb[3] - mu1) * r1 * g0.w + b0.w;
    or1[lane * 2 + 0] = o;
    o.x = (yb[4] - mu1) * r1 * g1.x + b1.x;
    o.y = (yb[5] - mu1) * r1 * g1.y + b1.y;
    o.z = (yb[6] - mu1) * r1 * g1.z + b1.z;
    o.w = (yb[7] - mu1) * r1 * g1.w + b1.w;
    or1[lane * 2 + 1] = o;
}

extern "C" void kernel_launch(void* const* d_in, const int* in_sizes, int n_in,
                              void* d_out, int out_size) {
    const float* x     = (const float*)d_in[0];
    const float* W     = (const float*)d_in[1];
    const float* bias  = (const float*)d_in[2];
    const float* gamma = (const float*)d_in[3];
    const float* beta  = (const float*)d_in[4];
    float* out = (float*)d_out;

    dim3 g1(BATCH, CHUNKS);
    col_sum_kernel<<<g1, 256>>>(x);
    mean_gemm_kernel<<<BATCH, CDIM>>>(W, bias);
    resid_ln_kernel<<<(BATCH * NROWS) / 16, 256>>>(x, gamma, beta, out);
}